// round 1
// baseline (speedup 1.0000x reference)
#include <cuda_runtime.h>
#include <cstdint>

// Problem constants (fixed by the dataset, but we read sizes dynamically):
//   child_val:    (1, 2,000,000) float32   -> d_in[0]
//   flat_indices: (32,000,000,)  int32     -> d_in[1]
//   segment_ids:  (32,000,000,)  int32 (sorted ascending) -> d_in[2]
//   num_nodes:    scalar int               -> d_in[3] (we use out_size instead)
//   out:          (1, 1,000,000) float32

static constexpr int EPT = 32;           // edges per thread
static constexpr int TPB = 256;          // threads per block

__global__ void zero_out_kernel(float4* __restrict__ out, int n4) {
    int i = blockIdx.x * blockDim.x + threadIdx.x;
    if (i < n4) out[i] = make_float4(0.f, 0.f, 0.f, 0.f);
}

__global__ __launch_bounds__(TPB) void segsum_kernel(
    const float* __restrict__ cv,
    const int*   __restrict__ fi,
    const int*   __restrict__ seg,
    float*       __restrict__ out,
    long long E)
{
    long long base = ((long long)blockIdx.x * TPB + threadIdx.x) * (long long)EPT;
    if (base >= E) return;

    // Fast path: full chunk, int4-aligned (base is a multiple of 32).
    if (base + EPT <= E) {
        int4  i4[EPT / 4];
        int4  s4[EPT / 4];
        float v [EPT];

        // Phase 1: stream all index vectors (independent loads -> high MLP)
        #pragma unroll
        for (int k = 0; k < EPT / 4; k++)
            i4[k] = *reinterpret_cast<const int4*>(fi + base + 4 * k);

        // Phase 2: issue all gathers (L2-resident table, independent loads)
        #pragma unroll
        for (int k = 0; k < EPT / 4; k++) {
            v[4 * k + 0] = __ldg(cv + i4[k].x);
            v[4 * k + 1] = __ldg(cv + i4[k].y);
            v[4 * k + 2] = __ldg(cv + i4[k].z);
            v[4 * k + 3] = __ldg(cv + i4[k].w);
        }

        // Phase 3: segment ids
        #pragma unroll
        for (int k = 0; k < EPT / 4; k++)
            s4[k] = *reinterpret_cast<const int4*>(seg + base + 4 * k);

        // Phase 4: run-length accumulate, atomic only at segment transitions.
        int   cur = s4[0].x;
        float acc = v[0];
        #pragma unroll
        for (int e = 1; e < EPT; e++) {
            int s = (e & 3) == 0 ? s4[e >> 2].x :
                    (e & 3) == 1 ? s4[e >> 2].y :
                    (e & 3) == 2 ? s4[e >> 2].z : s4[e >> 2].w;
            if (s != cur) {
                atomicAdd(out + cur, acc);
                cur = s;
                acc = v[e];
            } else {
                acc += v[e];
            }
        }
        atomicAdd(out + cur, acc);
    } else {
        // Tail path: scalar, bounds-checked.
        int   cur = -1;
        float acc = 0.f;
        for (long long e = base; e < E; e++) {
            int s = seg[e];
            float val = __ldg(cv + fi[e]);
            if (s != cur) {
                if (cur >= 0) atomicAdd(out + cur, acc);
                cur = s;
                acc = val;
            } else {
                acc += val;
            }
        }
        if (cur >= 0) atomicAdd(out + cur, acc);
    }
}

extern "C" void kernel_launch(void* const* d_in, const int* in_sizes, int n_in,
                              void* d_out, int out_size) {
    const float* cv  = (const float*)d_in[0];
    const int*   fi  = (const int*)d_in[1];
    const int*   seg = (const int*)d_in[2];
    float*       out = (float*)d_out;

    long long E = (long long)in_sizes[1];
    int N = out_size;  // batch(1) * num_nodes

    // Zero the output (poisoned by harness; empty segments must read 0).
    {
        int n4 = N / 4;
        int blocks = (n4 + TPB - 1) / TPB;
        zero_out_kernel<<<blocks, TPB>>>((float4*)out, n4);
        // handle N % 4 (N = 1,000,000 is divisible by 4; defensive anyway)
        // (scalar remainder folded into segsum correctness is unnecessary;
        //  if N%4 != 0 the last <4 elements are zeroed below)
    }

    long long threads_needed = (E + EPT - 1) / EPT;
    int blocks = (int)((threads_needed + TPB - 1) / TPB);
    segsum_kernel<<<blocks, TPB>>>(cv, fi, seg, out, E);
}

// round 2
// speedup vs baseline: 1.1663x; 1.1663x over previous
#include <cuda_runtime.h>
#include <cstdint>

// Problem shape (dataset-fixed, sizes read dynamically):
//   child_val:    (1, 2,000,000) float32   -> d_in[0]   (8MB, L2-resident)
//   flat_indices: (32,000,000,)  int32     -> d_in[1]   (streamed)
//   segment_ids:  (32,000,000,)  int32 sorted -> d_in[2] (streamed)
//   out:          (1, 1,000,000) float32
//
// Bottleneck model (from R1 ncu): L2 sector traffic ~1.3GB (32M gathers x 32B
// + 256MB streams) and ~32M divergent L1tex wavefronts -> structural floor
// ~115-120us. R1 ran 155us at occ=45.8% (regs=64). This round: EPT 32->16,
// __launch_bounds__ occupancy floor, to push L1/L2 from ~77% to ~90%.

static constexpr int EPT = 16;           // edges per thread
static constexpr int TPB = 256;          // threads per block

__global__ void zero_out_kernel(float4* __restrict__ out, int n4) {
    int i = blockIdx.x * blockDim.x + threadIdx.x;
    if (i < n4) out[i] = make_float4(0.f, 0.f, 0.f, 0.f);
}

__global__ __launch_bounds__(TPB, 6) void segsum_kernel(
    const float* __restrict__ cv,
    const int*   __restrict__ fi,
    const int*   __restrict__ seg,
    float*       __restrict__ out,
    long long E)
{
    long long base = ((long long)blockIdx.x * TPB + threadIdx.x) * (long long)EPT;
    if (base >= E) return;

    if (base + EPT <= E) {
        // Fast path: full chunk, int4-aligned (base is a multiple of 16).
        int4  i4[EPT / 4];
        int4  s4[EPT / 4];
        float v [EPT];

        // Phase 1: all index vectors first (front-batched -> high MLP).
        #pragma unroll
        for (int k = 0; k < EPT / 4; k++)
            i4[k] = *reinterpret_cast<const int4*>(fi + base + 4 * k);

        // Phase 2: all gathers (independent, L2-resident table).
        #pragma unroll
        for (int k = 0; k < EPT / 4; k++) {
            v[4 * k + 0] = __ldg(cv + i4[k].x);
            v[4 * k + 1] = __ldg(cv + i4[k].y);
            v[4 * k + 2] = __ldg(cv + i4[k].z);
            v[4 * k + 3] = __ldg(cv + i4[k].w);
        }

        // Phase 3: segment ids (independent of gathers; overlaps their latency).
        #pragma unroll
        for (int k = 0; k < EPT / 4; k++)
            s4[k] = *reinterpret_cast<const int4*>(seg + base + 4 * k);

        // Phase 4: run-length accumulate; one atomic per segment transition.
        int   cur = s4[0].x;
        float acc = v[0];
        #pragma unroll
        for (int e = 1; e < EPT; e++) {
            int s = (e & 3) == 0 ? s4[e >> 2].x :
                    (e & 3) == 1 ? s4[e >> 2].y :
                    (e & 3) == 2 ? s4[e >> 2].z : s4[e >> 2].w;
            if (s != cur) {
                atomicAdd(out + cur, acc);
                cur = s;
                acc = v[e];
            } else {
                acc += v[e];
            }
        }
        atomicAdd(out + cur, acc);
    } else {
        // Tail path: scalar, bounds-checked.
        int   cur = -1;
        float acc = 0.f;
        for (long long e = base; e < E; e++) {
            int s = seg[e];
            float val = __ldg(cv + fi[e]);
            if (s != cur) {
                if (cur >= 0) atomicAdd(out + cur, acc);
                cur = s;
                acc = val;
            } else {
                acc += val;
            }
        }
        if (cur >= 0) atomicAdd(out + cur, acc);
    }
}

extern "C" void kernel_launch(void* const* d_in, const int* in_sizes, int n_in,
                              void* d_out, int out_size) {
    const float* cv  = (const float*)d_in[0];
    const int*   fi  = (const int*)d_in[1];
    const int*   seg = (const int*)d_in[2];
    float*       out = (float*)d_out;

    long long E = (long long)in_sizes[1];
    int N = out_size;

    // Zero output (harness poisons to 0xAA; empty segments must read 0).
    {
        int n4 = N / 4;
        int blocks = (n4 + TPB - 1) / TPB;
        zero_out_kernel<<<blocks, TPB>>>((float4*)out, n4);
    }

    long long threads_needed = (E + EPT - 1) / EPT;
    int blocks = (int)((threads_needed + TPB - 1) / TPB);
    segsum_kernel<<<blocks, TPB>>>(cv, fi, seg, out, E);
}

// round 3
// speedup vs baseline: 1.2000x; 1.0289x over previous
#include <cuda_runtime.h>
#include <cstdint>

// Problem shape (dataset-fixed, sizes read dynamically):
//   child_val:    (1, 2,000,000) float32   -> d_in[0]   (8MB, L2-resident)
//   flat_indices: (32,000,000,)  int32     -> d_in[1]   (streamed)
//   segment_ids:  (32,000,000,)  int32 sorted -> d_in[2] (streamed)
//   out:          (1, 1,000,000) float32
//
// Bottleneck model (R1/R2 ncu): L1tex wavefront rate on the 32M divergent
// gathers -> ~120us structural floor. R2: 135.6us @ occ=67%, L1=85%.
// This round: EPT 16->8, __launch_bounds__(256,8) -> 64 warps/SM to keep
// the L1tex queue full and push L1 toward saturation.

static constexpr int EPT = 8;            // edges per thread
static constexpr int TPB = 256;          // threads per block

__global__ void zero_out_kernel(float4* __restrict__ out, int n4) {
    int i = blockIdx.x * blockDim.x + threadIdx.x;
    if (i < n4) out[i] = make_float4(0.f, 0.f, 0.f, 0.f);
}

__global__ __launch_bounds__(TPB, 8) void segsum_kernel(
    const float* __restrict__ cv,
    const int*   __restrict__ fi,
    const int*   __restrict__ seg,
    float*       __restrict__ out,
    long long E)
{
    long long base = ((long long)blockIdx.x * TPB + threadIdx.x) * (long long)EPT;
    if (base >= E) return;

    if (base + EPT <= E) {
        // Fast path: full chunk, int4-aligned (base is a multiple of 8).
        int4  i4[EPT / 4];
        int4  s4[EPT / 4];
        float v [EPT];

        // Phase 1: index vectors (front-batched -> MLP).
        #pragma unroll
        for (int k = 0; k < EPT / 4; k++)
            i4[k] = *reinterpret_cast<const int4*>(fi + base + 4 * k);

        // Phase 2: all gathers (independent; table is L2-resident).
        #pragma unroll
        for (int k = 0; k < EPT / 4; k++) {
            v[4 * k + 0] = __ldg(cv + i4[k].x);
            v[4 * k + 1] = __ldg(cv + i4[k].y);
            v[4 * k + 2] = __ldg(cv + i4[k].z);
            v[4 * k + 3] = __ldg(cv + i4[k].w);
        }

        // Phase 3: segment ids (overlap gather latency).
        #pragma unroll
        for (int k = 0; k < EPT / 4; k++)
            s4[k] = *reinterpret_cast<const int4*>(seg + base + 4 * k);

        // Phase 4: run-length accumulate; one atomic per segment transition.
        int   cur = s4[0].x;
        float acc = v[0];
        #pragma unroll
        for (int e = 1; e < EPT; e++) {
            int s = (e & 3) == 0 ? s4[e >> 2].x :
                    (e & 3) == 1 ? s4[e >> 2].y :
                    (e & 3) == 2 ? s4[e >> 2].z : s4[e >> 2].w;
            if (s != cur) {
                atomicAdd(out + cur, acc);
                cur = s;
                acc = v[e];
            } else {
                acc += v[e];
            }
        }
        atomicAdd(out + cur, acc);
    } else {
        // Tail path: scalar, bounds-checked.
        int   cur = -1;
        float acc = 0.f;
        for (long long e = base; e < E; e++) {
            int s = seg[e];
            float val = __ldg(cv + fi[e]);
            if (s != cur) {
                if (cur >= 0) atomicAdd(out + cur, acc);
                cur = s;
                acc = val;
            } else {
                acc += val;
            }
        }
        if (cur >= 0) atomicAdd(out + cur, acc);
    }
}

extern "C" void kernel_launch(void* const* d_in, const int* in_sizes, int n_in,
                              void* d_out, int out_size) {
    const float* cv  = (const float*)d_in[0];
    const int*   fi  = (const int*)d_in[1];
    const int*   seg = (const int*)d_in[2];
    float*       out = (float*)d_out;

    long long E = (long long)in_sizes[1];
    int N = out_size;

    // Zero output (harness poisons to 0xAA; empty segments must read 0).
    {
        int n4 = N / 4;
        int blocks = (n4 + TPB - 1) / TPB;
        zero_out_kernel<<<blocks, TPB>>>((float4*)out, n4);
    }

    long long threads_needed = (E + EPT - 1) / EPT;
    int blocks = (int)((threads_needed + TPB - 1) / TPB);
    segsum_kernel<<<blocks, TPB>>>(cv, fi, seg, out, E);
}

// round 4
// speedup vs baseline: 1.2587x; 1.0489x over previous
#include <cuda_runtime.h>
#include <cstdint>

// Problem shape (dataset-fixed, sizes read dynamically):
//   child_val:    (1, 2,000,000) float32   -> d_in[0]   (8MB, L2-resident)
//   flat_indices: (32,000,000,)  int32     -> d_in[1]
//   segment_ids:  (32,000,000,)  int32 sorted -> d_in[2]
//   out:          (1, 1,000,000) float32
//
// Bottleneck (R1-R3 ncu): L1tex/LSU wavefront pipe (~86% busy) shared by
// 32M divergent gathers + ~5M atomics. This round: warp-aggregated segmented
// scan cuts atomics to ~1.3M, relieving the saturated pipe.

static constexpr int EPT = 8;            // edges per thread
static constexpr int TPB = 256;          // threads per block
static constexpr unsigned FULL = 0xFFFFFFFFu;

__global__ void zero_out_kernel(float4* __restrict__ out, int n4) {
    int i = blockIdx.x * blockDim.x + threadIdx.x;
    if (i < n4) out[i] = make_float4(0.f, 0.f, 0.f, 0.f);
}

__global__ __launch_bounds__(TPB, 8) void segsum_kernel(
    const float* __restrict__ cv,
    const int*   __restrict__ fi,
    const int*   __restrict__ seg,
    float*       __restrict__ out,
    long long E)
{
    const int lane = threadIdx.x & 31;
    long long warp_gid  = ((long long)blockIdx.x * TPB + threadIdx.x) >> 5;
    long long warp_base = warp_gid * 32 * EPT;
    if (warp_base >= E) return;

    if (warp_base + 32 * EPT <= E) {
        // ---- Full-warp fast path ----
        long long base = warp_base + (long long)lane * EPT;

        int4  i4[EPT / 4];
        int4  s4[EPT / 4];
        float v [EPT];

        #pragma unroll
        for (int k = 0; k < EPT / 4; k++)
            i4[k] = *reinterpret_cast<const int4*>(fi + base + 4 * k);

        #pragma unroll
        for (int k = 0; k < EPT / 4; k++) {
            v[4 * k + 0] = __ldg(cv + i4[k].x);
            v[4 * k + 1] = __ldg(cv + i4[k].y);
            v[4 * k + 2] = __ldg(cv + i4[k].z);
            v[4 * k + 3] = __ldg(cv + i4[k].w);
        }

        #pragma unroll
        for (int k = 0; k < EPT / 4; k++)
            s4[k] = *reinterpret_cast<const int4*>(seg + base + 4 * k);

        int se[EPT];
        #pragma unroll
        for (int k = 0; k < EPT / 4; k++) {
            se[4 * k + 0] = s4[k].x; se[4 * k + 1] = s4[k].y;
            se[4 * k + 2] = s4[k].z; se[4 * k + 3] = s4[k].w;
        }

        // Per-thread run-length pass: head run, interior atomics, tail run.
        int   hs = se[0];  float ha = 0.f;      // head run (only if multi)
        bool  multi = false;
        int   cur = se[0]; float acc = v[0];
        #pragma unroll
        for (int e = 1; e < EPT; e++) {
            if (se[e] != cur) {
                if (!multi) { hs = cur; ha = acc; multi = true; }
                else        { atomicAdd(out + cur, acc); }   // interior run (rare)
                cur = se[e];
                acc = v[e];
            } else {
                acc += v[e];
            }
        }
        const int   ts = cur;   // tail run segment
        const float ta = acc;   // tail run partial

        // ---- Warp merge ----
        // conn: my first segment continues the previous lane's tail segment.
        const int myhead = multi ? hs : ts;
        const int ts_prev = __shfl_up_sync(FULL, ts, 1);
        const bool conn = (lane > 0) && (myhead == ts_prev);

        // Segmented inclusive scan over tail partials.
        // Chain continues through a lane only if that lane is single-run
        // and connected (its tail IS its head).
        float c = ta;
        int   hflag = !(conn && !multi);
        #pragma unroll
        for (int d = 1; d < 32; d <<= 1) {
            float c_up = __shfl_up_sync(FULL, c, d);
            int   h_up = __shfl_up_sync(FULL, hflag, d);
            if (lane >= d) {
                if (!hflag) c += c_up;
                hflag |= h_up;
            }
        }

        // Final scanned value of the previous lane (for multi-lane head merge).
        const float cprev    = __shfl_up_sync(FULL, c, 1);
        const int   conn_nxt = __shfl_down_sync(FULL, (int)conn, 1);

        // Multi-run lanes flush their head run (absorbing the incoming chain).
        if (multi)
            atomicAdd(out + hs, conn ? (ha + cprev) : ha);

        // Chain-end lanes flush the accumulated tail chain.
        if (lane == 31 || !conn_nxt)
            atomicAdd(out + ts, c);
    } else {
        // ---- Tail path: per-lane scalar, bounds-checked, direct atomics ----
        long long base = warp_base + (long long)lane * EPT;
        if (base >= E) return;
        long long end = base + EPT < E ? base + EPT : E;
        int   cur = -1;
        float acc = 0.f;
        for (long long e = base; e < end; e++) {
            int s = seg[e];
            float val = __ldg(cv + fi[e]);
            if (s != cur) {
                if (cur >= 0) atomicAdd(out + cur, acc);
                cur = s;
                acc = val;
            } else {
                acc += val;
            }
        }
        if (cur >= 0) atomicAdd(out + cur, acc);
    }
}

extern "C" void kernel_launch(void* const* d_in, const int* in_sizes, int n_in,
                              void* d_out, int out_size) {
    const float* cv  = (const float*)d_in[0];
    const int*   fi  = (const int*)d_in[1];
    const int*   seg = (const int*)d_in[2];
    float*       out = (float*)d_out;

    long long E = (long long)in_sizes[1];
    int N = out_size;

    // Zero output (harness poisons to 0xAA; empty segments must read 0).
    {
        int n4 = N / 4;
        int blocks = (n4 + TPB - 1) / TPB;
        zero_out_kernel<<<blocks, TPB>>>((float4*)out, n4);
    }

    long long threads_needed = (E + EPT - 1) / EPT;
    int blocks = (int)((threads_needed + TPB - 1) / TPB);
    segsum_kernel<<<blocks, TPB>>>(cv, fi, seg, out, E);
}

// round 5
// speedup vs baseline: 1.2818x; 1.0184x over previous
#include <cuda_runtime.h>
#include <cstdint>

// Problem shape (dataset-fixed, sizes read dynamically):
//   child_val:    (1, 2,000,000) float32   -> d_in[0]   (8MB, L2-resident)
//   flat_indices: (32,000,000,)  int32     -> d_in[1]
//   segment_ids:  (32,000,000,)  int32 sorted -> d_in[2]
//   out:          (1, 1,000,000) float32
//
// Bottleneck (R1-R4 ncu): L1tex wavefront pipe on 32M divergent gathers,
// with L2 sector traffic (~1.3GB) a close second. Warp-merged atomics (R4)
// got us to 124us vs ~115-120us structural floor. This round: gathers via
// ld.global.cg (skip L1 allocate/fill for ~97%-miss loads) + issue seg
// stream loads ahead of the index->gather dependent chain.

static constexpr int EPT = 8;            // edges per thread
static constexpr int TPB = 256;          // threads per block
static constexpr unsigned FULL = 0xFFFFFFFFu;

__global__ void zero_out_kernel(float4* __restrict__ out, int n4) {
    int i = blockIdx.x * blockDim.x + threadIdx.x;
    if (i < n4) out[i] = make_float4(0.f, 0.f, 0.f, 0.f);
}

__global__ __launch_bounds__(TPB, 8) void segsum_kernel(
    const float* __restrict__ cv,
    const int*   __restrict__ fi,
    const int*   __restrict__ seg,
    float*       __restrict__ out,
    long long E)
{
    const int lane = threadIdx.x & 31;
    long long warp_gid  = ((long long)blockIdx.x * TPB + threadIdx.x) >> 5;
    long long warp_base = warp_gid * 32 * EPT;
    if (warp_base >= E) return;

    if (warp_base + 32 * EPT <= E) {
        // ---- Full-warp fast path ----
        long long base = warp_base + (long long)lane * EPT;

        int4  i4[EPT / 4];
        int4  s4[EPT / 4];
        float v [EPT];

        // Phase 0: seg vectors first — independent, stay in flight under
        // the whole index->gather chain.
        #pragma unroll
        for (int k = 0; k < EPT / 4; k++)
            s4[k] = *reinterpret_cast<const int4*>(seg + base + 4 * k);

        // Phase 1: index vectors.
        #pragma unroll
        for (int k = 0; k < EPT / 4; k++)
            i4[k] = *reinterpret_cast<const int4*>(fi + base + 4 * k);

        // Phase 2: gathers, L2-only (.cg): table is 8MB -> ~97% L1 miss,
        // skip L1 allocate/fill work on the saturated L1tex pipe.
        #pragma unroll
        for (int k = 0; k < EPT / 4; k++) {
            v[4 * k + 0] = __ldcg(cv + i4[k].x);
            v[4 * k + 1] = __ldcg(cv + i4[k].y);
            v[4 * k + 2] = __ldcg(cv + i4[k].z);
            v[4 * k + 3] = __ldcg(cv + i4[k].w);
        }

        int se[EPT];
        #pragma unroll
        for (int k = 0; k < EPT / 4; k++) {
            se[4 * k + 0] = s4[k].x; se[4 * k + 1] = s4[k].y;
            se[4 * k + 2] = s4[k].z; se[4 * k + 3] = s4[k].w;
        }

        // Per-thread run-length pass: head run, interior atomics, tail run.
        int   hs = se[0];  float ha = 0.f;      // head run (only if multi)
        bool  multi = false;
        int   cur = se[0]; float acc = v[0];
        #pragma unroll
        for (int e = 1; e < EPT; e++) {
            if (se[e] != cur) {
                if (!multi) { hs = cur; ha = acc; multi = true; }
                else        { atomicAdd(out + cur, acc); }   // interior run (rare)
                cur = se[e];
                acc = v[e];
            } else {
                acc += v[e];
            }
        }
        const int   ts = cur;   // tail run segment
        const float ta = acc;   // tail run partial

        // ---- Warp merge ----
        // conn: my first segment continues the previous lane's tail segment.
        const int myhead = multi ? hs : ts;
        const int ts_prev = __shfl_up_sync(FULL, ts, 1);
        const bool conn = (lane > 0) && (myhead == ts_prev);

        // Segmented inclusive scan over tail partials. Chain continues
        // through a lane only if it is single-run and connected.
        float c = ta;
        int   hflag = !(conn && !multi);
        #pragma unroll
        for (int d = 1; d < 32; d <<= 1) {
            float c_up = __shfl_up_sync(FULL, c, d);
            int   h_up = __shfl_up_sync(FULL, hflag, d);
            if (lane >= d) {
                if (!hflag) c += c_up;
                hflag |= h_up;
            }
        }

        // Scanned value of the previous lane (for multi-lane head merge).
        const float cprev    = __shfl_up_sync(FULL, c, 1);
        const int   conn_nxt = __shfl_down_sync(FULL, (int)conn, 1);

        // Multi-run lanes flush their head run (absorbing incoming chain).
        if (multi)
            atomicAdd(out + hs, conn ? (ha + cprev) : ha);

        // Chain-end lanes flush the accumulated tail chain.
        if (lane == 31 || !conn_nxt)
            atomicAdd(out + ts, c);
    } else {
        // ---- Tail path: per-lane scalar, bounds-checked, direct atomics ----
        long long base = warp_base + (long long)lane * EPT;
        if (base >= E) return;
        long long end = base + EPT < E ? base + EPT : E;
        int   cur = -1;
        float acc = 0.f;
        for (long long e = base; e < end; e++) {
            int s = seg[e];
            float val = __ldcg(cv + fi[e]);
            if (s != cur) {
                if (cur >= 0) atomicAdd(out + cur, acc);
                cur = s;
                acc = val;
            } else {
                acc += val;
            }
        }
        if (cur >= 0) atomicAdd(out + cur, acc);
    }
}

extern "C" void kernel_launch(void* const* d_in, const int* in_sizes, int n_in,
                              void* d_out, int out_size) {
    const float* cv  = (const float*)d_in[0];
    const int*   fi  = (const int*)d_in[1];
    const int*   seg = (const int*)d_in[2];
    float*       out = (float*)d_out;

    long long E = (long long)in_sizes[1];
    int N = out_size;

    // Zero output (harness poisons to 0xAA; empty segments must read 0).
    {
        int n4 = N / 4;
        int blocks = (n4 + TPB - 1) / TPB;
        zero_out_kernel<<<blocks, TPB>>>((float4*)out, n4);
    }

    long long threads_needed = (E + EPT - 1) / EPT;
    int blocks = (int)((threads_needed + TPB - 1) / TPB);
    segsum_kernel<<<blocks, TPB>>>(cv, fi, seg, out, E);
}